// round 12
// baseline (speedup 1.0000x reference)
#include <cuda_runtime.h>

// Problem constants (fixed by setup_inputs)
#define B_    4
#define C_    256
#define H_    256
#define W_    512
#define FS    14
#define NP    (FS*FS)        // 196
#define NROI  400            // B * MAXLOAD
#define HW    (H_*W_)        // 131072
#define HB    (B_*H_)        // 1024 stacked rows
#define KCH   4              // channels per thread
#define NCQ   (C_/KCH)       // 64 channel groups
#define NSM   148
#define CHUNK (NSM*8)        // 1184 blocks ~ one wave

#define THREADS 256

static const long OUT_MAIN   = (long)NROI * C_ * NP;      // 20,070,400
#define MAIN_THREADS (NROI * NCQ * NP)                    // 5,017,600
#define MAIN_BLOCKS  (MAIN_THREADS / THREADS)             // 19,600 (exact)

__device__ int g_perm[NROI];

// ---- kernel 1: rank-sort ROIs by (batch, y-center); O(N^2), one block ----
__global__ void sort_kernel(const float* __restrict__ rois)
{
    __shared__ float key[NROI];
    int t = threadIdx.x;
    if (t < NROI) {
        float4 r = reinterpret_cast<const float4*>(rois)[t];
        key[t] = (r.y + r.w) * 0.5f + (float)(t / 100) * 4096.0f;
    }
    __syncthreads();
    if (t < NROI) {
        float k = key[t];
        int rank = 0;
        for (int m = 0; m < NROI; m++) {
            float km = key[m];
            rank += (km < k) || (km == k && m < t);
        }
        g_perm[rank] = t;
    }
}

// ---- kernel 2: main pooler ----
__global__ __launch_bounds__(THREADS)
void pooler_sorted_kernel(const float* __restrict__ feat,
                          const float* __restrict__ rois,
                          float*       __restrict__ out,
                          long out_size)
{
    int blk = blockIdx.x;
    int tid = threadIdx.x;

    // Tail: val_bind = repeat(arange(B), MAXLOAD) appended after main output.
    if (blk >= MAIN_BLOCKS) {
        long k   = (long)(blk - MAIN_BLOCKS) * THREADS + tid;
        long idx = OUT_MAIN + k;
        if (idx < out_size) out[idx] = (float)((int)(k / 100));
        return;
    }

    // SM-affinity transpose within each ~wave-sized chunk:
    // co-resident / sequential CTAs on one SM (bids = mod 148) get
    // CONSECUTIVE work indices -> consecutive sorted ROIs -> L1 row reuse.
    int chunk = blk / CHUNK;
    int rr    = blk - chunk * CHUNK;
    int base  = chunk * CHUNK;
    int size  = min(CHUNK, MAIN_BLOCKS - base);
    int cols  = size / NSM;
    int rem   = size - cols * NSM;
    int sm    = rr % NSM;
    int idx   = rr / NSM;
    int w     = base + ((sm < rem) ? sm * (cols + 1) + idx
                                   : rem * (cols + 1) + (sm - rem) * cols + idx);

    int t = w * THREADS + tid;

    // Decode: p fastest (warp coalescing), n middle (SORTED), cq SLOWEST
    // (channel-slab ordering: a wave covers all ROIs in a narrow slab)
    int p  = t % NP;
    int q  = t / NP;
    int ns = q % NROI;
    int cq = q / NROI;
    int n  = g_perm[ns];
    int c  = cq * KCH;
    int i  = p / FS;
    int j  = p - i * FS;
    int b  = n / 100;                         // roi's batch

    const float4 r = reinterpret_cast<const float4*>(rois)[n];
    const float inv13 = 1.0f / 13.0f;

    float scalex = r.z - r.x;
    float scaley = r.w - r.y;
    float biasy  = r.y + (float)b * 1024.0f;  // image_height

    float gridx = ((float)j * inv13 * scalex + r.x)  * 0.25f;  // /shrink_scale
    float gridy = ((float)i * inv13 * scaley + biasy) * 0.25f;

    // normalized-grid round trip, exactly as reference
    float gx = (gridx * (1.0f / (W_ - 1)) - 0.5f) * 2.0f;
    float gy = (gridy * (1.0f / (HB - 1)) - 0.5f) * 2.0f;
    float px = ((gx + 1.0f) * (float)W_ - 1.0f) * 0.5f;
    float py = ((gy + 1.0f) * (float)HB - 1.0f) * 0.5f;
    px = fminf(fmaxf(px, 0.0f), (float)(W_ - 1));
    py = fminf(fmaxf(py, 0.0f), (float)(HB - 1));

    float x0f = floorf(px);
    float y0f = floorf(py);
    float wx  = px - x0f;
    float wy  = py - y0f;
    int x0 = (int)x0f;
    int y0 = (int)y0f;
    int x1 = min(x0 + 1, W_ - 1);
    int y1 = min(y0 + 1, HB - 1);

    // feats view (C, B*H, W); element indices fit in int32 (max ~134M)
    int a0 = ((y0 >> 8) * C_ + c) * HW + (y0 & 255) * W_;
    int a1 = ((y1 >> 8) * C_ + c) * HW + (y1 & 255) * W_;

    // Front-batched independent loads (16 LDG.32)
    float f00[KCH], f01[KCH], f10[KCH], f11[KCH];
#pragma unroll
    for (int k = 0; k < KCH; k++) {
        int o = k * HW;
        f00[k] = __ldg(feat + a0 + o + x0);
        f01[k] = __ldg(feat + a0 + o + x1);
        f10[k] = __ldg(feat + a1 + o + x0);
        f11[k] = __ldg(feat + a1 + o + x1);
    }

    float omwx = 1.0f - wx;
    float omwy = 1.0f - wy;
    long ob = ((long)(n * C_ + c)) * NP + p;
#pragma unroll
    for (int k = 0; k < KCH; k++) {
        float v = (f00[k] * omwx + f01[k] * wx) * omwy
                + (f10[k] * omwx + f11[k] * wx) * wy;
        // Streaming store: output is write-once; keep L2 for features.
        __stcs(&out[ob + (long)k * NP], v);
    }
}

extern "C" void kernel_launch(void* const* d_in, const int* in_sizes, int n_in,
                              void* d_out, int out_size)
{
    const float* feat = (const float*)d_in[0];
    const float* rois = (const float*)d_in[1];
    float* out = (float*)d_out;

    long tail = (long)out_size - OUT_MAIN;
    int tail_blocks = tail > 0 ? (int)((tail + THREADS - 1) / THREADS) : 0;

    sort_kernel<<<1, 512>>>(rois);
    pooler_sorted_kernel<<<MAIN_BLOCKS + tail_blocks, THREADS>>>(
        feat, rois, out, (long)out_size);
}

// round 13
// speedup vs baseline: 1.2034x; 1.2034x over previous
#include <cuda_runtime.h>

// Problem constants (fixed by setup_inputs)
#define B_    4
#define C_    256
#define H_    256
#define W_    512
#define FS    14
#define NP    (FS*FS)        // 196
#define NROI  400            // B * MAXLOAD
#define HW    (H_*W_)        // 131072
#define HB    (B_*H_)        // 1024 stacked rows
#define KCH   4              // channels per thread
#define NCQ   (C_/KCH)       // 64 channel groups

#define THREADS 256

#define OUT_MAIN_I   20070400                             // NROI*C_*NP (fits int32)
#define MAIN_THREADS (NROI * NCQ * NP)                    // 5,017,600
#define MAIN_BLOCKS  (MAIN_THREADS / THREADS)             // 19,600 (exact)

__global__ __launch_bounds__(THREADS)
void pooler_final_kernel(const float* __restrict__ feat,
                         const float* __restrict__ rois,
                         float*       __restrict__ out,
                         int out_size)
{
    int t = blockIdx.x * THREADS + threadIdx.x;

    // Tail: val_bind = repeat(arange(B), MAXLOAD) appended after main output.
    if (t >= MAIN_THREADS) {
        int k   = t - MAIN_THREADS;
        int idx = OUT_MAIN_I + k;
        if (idx < out_size) out[idx] = (float)(k / 100);
        return;
    }

    // Decode: p fastest (warp coalescing), n middle, cq SLOWEST.
    // A concurrent wave covers ALL ROIs within a narrow channel slab ->
    // cross-ROI overlaps hit in L2 instead of re-missing to DRAM.
    int p  = t % NP;
    int q  = t / NP;
    int n  = q % NROI;
    int cq = q / NROI;
    int c  = cq * KCH;
    int i  = p / FS;
    int j  = p - i * FS;
    int b  = n / 100;                         // roi's batch

    const float4 r = reinterpret_cast<const float4*>(rois)[n];
    const float inv13 = 1.0f / 13.0f;

    float scalex = r.z - r.x;
    float scaley = r.w - r.y;
    float biasy  = r.y + (float)b * 1024.0f;  // image_height

    float gridx = ((float)j * inv13 * scalex + r.x)  * 0.25f;  // /shrink_scale
    float gridy = ((float)i * inv13 * scaley + biasy) * 0.25f;

    // normalized-grid round trip, exactly as reference
    float gx = (gridx * (1.0f / (W_ - 1)) - 0.5f) * 2.0f;
    float gy = (gridy * (1.0f / (HB - 1)) - 0.5f) * 2.0f;
    float px = ((gx + 1.0f) * (float)W_ - 1.0f) * 0.5f;
    float py = ((gy + 1.0f) * (float)HB - 1.0f) * 0.5f;
    px = fminf(fmaxf(px, 0.0f), (float)(W_ - 1));
    py = fminf(fmaxf(py, 0.0f), (float)(HB - 1));

    float x0f = floorf(px);
    float y0f = floorf(py);
    float wx  = px - x0f;
    float wy  = py - y0f;
    int x0 = (int)x0f;
    int y0 = (int)y0f;
    int x1 = min(x0 + 1, W_ - 1);
    int y1 = min(y0 + 1, HB - 1);

    // feats view (C, B*H, W); element indices fit in int32 (max ~134M)
    int a0 = ((y0 >> 8) * C_ + c) * HW + (y0 & 255) * W_;
    int a1 = ((y1 >> 8) * C_ + c) * HW + (y1 & 255) * W_;

    // Front-batched independent loads (16 LDG.32)
    float f00[KCH], f01[KCH], f10[KCH], f11[KCH];
#pragma unroll
    for (int k = 0; k < KCH; k++) {
        int o = k * HW;
        f00[k] = __ldg(feat + a0 + o + x0);
        f01[k] = __ldg(feat + a0 + o + x1);
        f10[k] = __ldg(feat + a1 + o + x0);
        f11[k] = __ldg(feat + a1 + o + x1);
    }

    float omwx = 1.0f - wx;
    float omwy = 1.0f - wy;
    int ob = (n * C_ + c) * NP + p;           // max ~20.07M: int32-safe
#pragma unroll
    for (int k = 0; k < KCH; k++) {
        float v = (f00[k] * omwx + f01[k] * wx) * omwy
                + (f10[k] * omwx + f11[k] * wx) * wy;
        // Streaming store: output is write-once, never re-read.
        // Evict-first keeps L2 capacity for cross-ROI feature reuse.
        __stcs(&out[ob + k * NP], v);
    }
}

extern "C" void kernel_launch(void* const* d_in, const int* in_sizes, int n_in,
                              void* d_out, int out_size)
{
    const float* feat = (const float*)d_in[0];
    const float* rois = (const float*)d_in[1];
    float* out = (float*)d_out;

    long tail = (long)out_size - (long)OUT_MAIN_I;
    int tail_blocks = tail > 0 ? (int)((tail + THREADS - 1) / THREADS) : 0;

    pooler_final_kernel<<<MAIN_BLOCKS + tail_blocks, THREADS>>>(
        feat, rois, out, out_size);
}